// round 2
// baseline (speedup 1.0000x reference)
#include <cuda_runtime.h>
#include <cstdint>

// Problem constants (fixed by reference)
#define NUM_USERS  100000
#define NUM_ITEMS  50000
#define N_TOTAL    150100
#define EMBED_DIM  64
#define VEC_PER_ROW (EMBED_DIM / 4)   // 16 float4 per node row
#define N4_TOTAL   (N_TOTAL * VEC_PER_ROW)

// Scratch: ping-pong embedding buffers + accumulator (zero-init module globals;
// no runtime allocation).
__device__ float4 g_bufA[N4_TOTAL];
__device__ float4 g_bufB[N4_TOTAL];
__device__ float4 g_acc [N4_TOTAL];

// ---------------------------------------------------------------------------
// Vector reduction helper: red.global.add.v4.f32 (no return value, fire+forget)
// ---------------------------------------------------------------------------
__device__ __forceinline__ void red_add_v4(float4* addr, float4 v) {
    asm volatile("red.global.add.v4.f32 [%0], {%1, %2, %3, %4};"
                 :: "l"(addr), "f"(v.x), "f"(v.y), "f"(v.z), "f"(v.w)
                 : "memory");
}

// ---------------------------------------------------------------------------
// init: acc = node_emb ; bufA = 0
// ---------------------------------------------------------------------------
__global__ void init_kernel(const float4* __restrict__ emb) {
    int i = blockIdx.x * blockDim.x + threadIdx.x;
    if (i >= N4_TOTAL) return;
    g_acc[i]  = emb[i];
    g_bufA[i] = make_float4(0.f, 0.f, 0.f, 0.f);
}

// ---------------------------------------------------------------------------
// acc += src ; dst_zero = 0   (fused accumulate + zeroing of next layer buffer)
// ---------------------------------------------------------------------------
__global__ void acc_zero_kernel(const float4* __restrict__ src,
                                float4* __restrict__ dst_zero) {
    int i = blockIdx.x * blockDim.x + threadIdx.x;
    if (i >= N4_TOTAL) return;
    float4 a = g_acc[i];
    float4 s = src[i];
    a.x += s.x; a.y += s.y; a.z += s.z; a.w += s.w;
    g_acc[i] = a;
    dst_zero[i] = make_float4(0.f, 0.f, 0.f, 0.f);
}

// ---------------------------------------------------------------------------
// SpMM scatter: for each edge e: out[row[e]] += val[e] * in[col[e]]
// 16 threads per edge, one float4 (16B) per lane -> 256B contiguous per edge.
// ---------------------------------------------------------------------------
__global__ void scatter_kernel(const float4* __restrict__ in,
                               float4* __restrict__ out,
                               const int*   __restrict__ adj_row,
                               const int*   __restrict__ adj_col,
                               const float* __restrict__ adj_val,
                               int n_edges) {
    long long t = (long long)blockIdx.x * blockDim.x + threadIdx.x;
    int e    = (int)(t >> 4);
    int lane = (int)(t & 15);
    if (e >= n_edges) return;

    int   r = __ldg(adj_row + e);
    int   c = __ldg(adj_col + e);
    float v = __ldg(adj_val + e);

    float4 x = __ldg(in + (long long)c * VEC_PER_ROW + lane);
    float4 m = make_float4(x.x * v, x.y * v, x.z * v, x.w * v);
    red_add_v4(out + (long long)r * VEC_PER_ROW + lane, m);
}

// ---------------------------------------------------------------------------
// Final: out[p] = dot( (acc_u + last_u)/4 , (acc_i + last_i)/4 )
// 16 lanes per pair, shfl-reduce over the 16-lane group.
// ---------------------------------------------------------------------------
__global__ void final_kernel(const float4* __restrict__ last,   // layer-3 output
                             const int* __restrict__ user_ids,
                             const int* __restrict__ item_ids,
                             float* __restrict__ out,
                             int n_pairs) {
    int t    = blockIdx.x * blockDim.x + threadIdx.x;
    int p    = t >> 4;
    int lane = t & 15;
    if (p >= n_pairs) return;

    int urow = __ldg(user_ids + p);
    int irow = NUM_USERS + __ldg(item_ids + p);

    long long uo = (long long)urow * VEC_PER_ROW + lane;
    long long io = (long long)irow * VEC_PER_ROW + lane;

    float4 ua = g_acc[uo], ul = last[uo];
    float4 ia = g_acc[io], il = last[io];

    float4 u = make_float4(ua.x + ul.x, ua.y + ul.y, ua.z + ul.z, ua.w + ul.w);
    float4 i4 = make_float4(ia.x + il.x, ia.y + il.y, ia.z + il.z, ia.w + il.w);

    float partial = u.x * i4.x + u.y * i4.y + u.z * i4.z + u.w * i4.w;

    // reduce within the 16-lane group
    unsigned mask = 0xFFFFFFFFu;
    #pragma unroll
    for (int off = 8; off > 0; off >>= 1)
        partial += __shfl_down_sync(mask, partial, off);

    if (lane == 0)
        out[p] = partial * (1.0f / 16.0f);   // (1/4)*(1/4) scaling
}

// ---------------------------------------------------------------------------
// Launch
// ---------------------------------------------------------------------------
extern "C" void kernel_launch(void* const* d_in, const int* in_sizes, int n_in,
                              void* d_out, int out_size) {
    const float4* node_emb = (const float4*)d_in[0];
    const float*  adj_val  = (const float*)d_in[1];
    const int*    adj_row  = (const int*)d_in[2];
    const int*    adj_col  = (const int*)d_in[3];
    const int*    user_ids = (const int*)d_in[4];
    const int*    item_ids = (const int*)d_in[5];
    float*        out      = (float*)d_out;

    int n_edges = in_sizes[1];
    int n_pairs = out_size;

    float4 *bufA, *bufB;
    cudaGetSymbolAddress((void**)&bufA, g_bufA);
    cudaGetSymbolAddress((void**)&bufB, g_bufB);

    const int TB = 256;
    int elem_blocks = (N4_TOTAL + TB - 1) / TB;
    long long scat_threads = (long long)n_edges * 16;
    int scat_blocks = (int)((scat_threads + TB - 1) / TB);
    int pair_blocks = (n_pairs * 16 + TB - 1) / TB;

    // acc = node_emb, bufA = 0
    init_kernel<<<elem_blocks, TB>>>(node_emb);

    // layer 1: node_emb -> bufA
    scatter_kernel<<<scat_blocks, TB>>>(node_emb, bufA, adj_row, adj_col, adj_val, n_edges);
    // acc += bufA ; bufB = 0
    acc_zero_kernel<<<elem_blocks, TB>>>(bufA, bufB);

    // layer 2: bufA -> bufB
    scatter_kernel<<<scat_blocks, TB>>>(bufA, bufB, adj_row, adj_col, adj_val, n_edges);
    // acc += bufB ; bufA = 0
    acc_zero_kernel<<<elem_blocks, TB>>>(bufB, bufA);

    // layer 3: bufB -> bufA   (bufA folded into the final gather, not into acc)
    scatter_kernel<<<scat_blocks, TB>>>(bufB, bufA, adj_row, adj_col, adj_val, n_edges);

    // out[p] = dot((acc_u + bufA_u)/4, (acc_i + bufA_i)/4)
    final_kernel<<<pair_blocks, TB>>>(bufA, user_ids, item_ids, out, n_pairs);
}

// round 4
// speedup vs baseline: 1.6054x; 1.6054x over previous
#include <cuda_runtime.h>
#include <cstdint>

#define NUM_USERS  100000
#define NUM_ITEMS  50000
#define N_TOTAL    150100
#define EMBED_DIM  64
#define VEC_PER_ROW (EMBED_DIM / 4)            // 16 float4 per node row
#define N4_TOTAL   (N_TOTAL * VEC_PER_ROW)
#define MAX_EDGES  3000000

// ---------------- device scratch (no runtime allocation) -------------------
__device__ int    g_count  [N_TOTAL];
__device__ int    g_offsets[N_TOTAL];
__device__ int    g_cursor [N_TOTAL];
__device__ int2   g_pedge  [MAX_EDGES];        // {col, val-bits} packed, row-sorted
__device__ float4 g_bufA[N4_TOTAL];
__device__ float4 g_bufB[N4_TOTAL];
__device__ float4 g_acc [N4_TOTAL];

// ---------------------------------------------------------------------------
// CSR build: zero counts -> histogram -> exclusive scan -> permute edges
// ---------------------------------------------------------------------------
__global__ void zero_count_kernel() {
    int i = blockIdx.x * blockDim.x + threadIdx.x;
    if (i < N_TOTAL) g_count[i] = 0;
}

__global__ void hist_kernel(const int* __restrict__ adj_row, int n_edges) {
    int e = blockIdx.x * blockDim.x + threadIdx.x;
    if (e < n_edges) atomicAdd(&g_count[adj_row[e]], 1);
}

// Single-block exclusive scan over g_count, 4 elements/thread per chunk.
// Writes g_offsets and initializes g_cursor = g_offsets.
#define SCAN_T 1024
__global__ void scan_kernel() {
    __shared__ int wsum[32];
    __shared__ int s_carry;
    int tid = threadIdx.x;
    if (tid == 0) s_carry = 0;
    __syncthreads();

    const int CHUNK = SCAN_T * 4;
    for (int base = 0; base < N_TOTAL; base += CHUNK) {
        int idx = base + tid * 4;
        int a[4]; int sum = 0;
        #pragma unroll
        for (int k = 0; k < 4; k++) {
            int i = idx + k;
            a[k] = (i < N_TOTAL) ? g_count[i] : 0;
            sum += a[k];
        }
        // inclusive warp scan of per-thread sums
        int v = sum;
        #pragma unroll
        for (int off = 1; off < 32; off <<= 1) {
            int n = __shfl_up_sync(0xffffffffu, v, off);
            if ((tid & 31) >= off) v += n;
        }
        if ((tid & 31) == 31) wsum[tid >> 5] = v;
        __syncthreads();
        if (tid < 32) {
            int w = wsum[tid];
            #pragma unroll
            for (int off = 1; off < 32; off <<= 1) {
                int n = __shfl_up_sync(0xffffffffu, w, off);
                if (tid >= off) w += n;
            }
            wsum[tid] = w;
        }
        __syncthreads();
        int incl = v + ((tid >= 32) ? wsum[(tid >> 5) - 1] : 0);
        int run  = s_carry + incl - sum;      // exclusive base for this thread
        #pragma unroll
        for (int k = 0; k < 4; k++) {
            int i = idx + k;
            if (i < N_TOTAL) { g_offsets[i] = run; g_cursor[i] = run; }
            run += a[k];
        }
        __syncthreads();
        if (tid == SCAN_T - 1) s_carry += incl;   // incl of last thread = chunk total
        __syncthreads();
    }
}

__global__ void fill_kernel(const int* __restrict__ adj_row,
                            const int* __restrict__ adj_col,
                            const float* __restrict__ adj_val,
                            int n_edges) {
    int e = blockIdx.x * blockDim.x + threadIdx.x;
    if (e >= n_edges) return;
    int r = adj_row[e];
    int p = atomicAdd(&g_cursor[r], 1);
    g_pedge[p] = make_int2(adj_col[e], __float_as_int(adj_val[e]));
}

// ---------------------------------------------------------------------------
// CSR SpMM: out[r] = sum_{edges of r} val * in[col].
// 16 lanes per row, each lane owns one float4 (register accumulation, no
// atomics). Output written exactly once, 256B coalesced per row.
// ---------------------------------------------------------------------------
__global__ void spmm_csr_kernel(const float4* __restrict__ in,
                                float4* __restrict__ out) {
    int t    = blockIdx.x * blockDim.x + threadIdx.x;
    int r    = t >> 4;
    int lane = t & 15;
    if (r >= N_TOTAL) return;

    int beg = __ldg(&g_offsets[r]);
    int cnt = __ldg(&g_count[r]);

    float4 acc = make_float4(0.f, 0.f, 0.f, 0.f);
    int j = 0;
    // unroll-by-2 with simple software pipelining
    for (; j + 1 < cnt; j += 2) {
        int2 e0 = __ldg(&g_pedge[beg + j]);
        int2 e1 = __ldg(&g_pedge[beg + j + 1]);
        float4 x0 = __ldg(in + (long long)e0.x * VEC_PER_ROW + lane);
        float4 x1 = __ldg(in + (long long)e1.x * VEC_PER_ROW + lane);
        float v0 = __int_as_float(e0.y);
        float v1 = __int_as_float(e1.y);
        acc.x += v0 * x0.x; acc.y += v0 * x0.y; acc.z += v0 * x0.z; acc.w += v0 * x0.w;
        acc.x += v1 * x1.x; acc.y += v1 * x1.y; acc.z += v1 * x1.z; acc.w += v1 * x1.w;
    }
    if (j < cnt) {
        int2 e0 = __ldg(&g_pedge[beg + j]);
        float4 x0 = __ldg(in + (long long)e0.x * VEC_PER_ROW + lane);
        float v0 = __int_as_float(e0.y);
        acc.x += v0 * x0.x; acc.y += v0 * x0.y; acc.z += v0 * x0.z; acc.w += v0 * x0.w;
    }
    out[(long long)r * VEC_PER_ROW + lane] = acc;
}

// ---------------------------------------------------------------------------
// acc = emb + l1 + l2   (single fused pass)
// ---------------------------------------------------------------------------
__global__ void acc3_kernel(const float4* __restrict__ emb,
                            const float4* __restrict__ l1,
                            const float4* __restrict__ l2) {
    int i = blockIdx.x * blockDim.x + threadIdx.x;
    if (i >= N4_TOTAL) return;
    float4 a = emb[i], b = l1[i], c = l2[i];
    a.x += b.x + c.x; a.y += b.y + c.y; a.z += b.z + c.z; a.w += b.w + c.w;
    g_acc[i] = a;
}

// ---------------------------------------------------------------------------
// out[p] = dot((acc_u + l3_u)/4, (acc_i + l3_i)/4)
// ---------------------------------------------------------------------------
__global__ void final_kernel(const float4* __restrict__ l3,
                             const int* __restrict__ user_ids,
                             const int* __restrict__ item_ids,
                             float* __restrict__ out,
                             int n_pairs) {
    int t    = blockIdx.x * blockDim.x + threadIdx.x;
    int p    = t >> 4;
    int lane = t & 15;
    if (p >= n_pairs) return;

    int urow = __ldg(user_ids + p);
    int irow = NUM_USERS + __ldg(item_ids + p);

    long long uo = (long long)urow * VEC_PER_ROW + lane;
    long long io = (long long)irow * VEC_PER_ROW + lane;

    float4 ua = g_acc[uo], ul = l3[uo];
    float4 ia = g_acc[io], il = l3[io];

    float4 u  = make_float4(ua.x + ul.x, ua.y + ul.y, ua.z + ul.z, ua.w + ul.w);
    float4 iv = make_float4(ia.x + il.x, ia.y + il.y, ia.z + il.z, ia.w + il.w);

    float partial = u.x * iv.x + u.y * iv.y + u.z * iv.z + u.w * iv.w;

    #pragma unroll
    for (int off = 8; off > 0; off >>= 1)
        partial += __shfl_down_sync(0xffffffffu, partial, off);

    if (lane == 0)
        out[p] = partial * (1.0f / 16.0f);
}

// ---------------------------------------------------------------------------
// Launch
// ---------------------------------------------------------------------------
extern "C" void kernel_launch(void* const* d_in, const int* in_sizes, int n_in,
                              void* d_out, int out_size) {
    const float4* node_emb = (const float4*)d_in[0];
    const float*  adj_val  = (const float*)d_in[1];
    const int*    adj_row  = (const int*)d_in[2];
    const int*    adj_col  = (const int*)d_in[3];
    const int*    user_ids = (const int*)d_in[4];
    const int*    item_ids = (const int*)d_in[5];
    float*        out      = (float*)d_out;

    int n_edges = in_sizes[1];
    int n_pairs = out_size;

    float4 *bufA, *bufB;
    cudaGetSymbolAddress((void**)&bufA, g_bufA);
    cudaGetSymbolAddress((void**)&bufB, g_bufB);

    const int TB = 256;
    int node_blocks = (N_TOTAL + TB - 1) / TB;
    int elem_blocks = (N4_TOTAL + TB - 1) / TB;
    int edge_blocks = (n_edges + TB - 1) / TB;
    int row_blocks  = (N_TOTAL * 16 + TB - 1) / TB;
    int pair_blocks = (n_pairs * 16 + TB - 1) / TB;

    // --- CSR build (once per launch, reused by all 3 layers) ---
    zero_count_kernel<<<node_blocks, TB>>>();
    hist_kernel<<<edge_blocks, TB>>>(adj_row, n_edges);
    scan_kernel<<<1, SCAN_T>>>();
    fill_kernel<<<edge_blocks, TB>>>(adj_row, adj_col, adj_val, n_edges);

    // --- 3 propagation layers, register-accumulated (no atomics) ---
    spmm_csr_kernel<<<row_blocks, TB>>>(node_emb, bufA);   // l1
    spmm_csr_kernel<<<row_blocks, TB>>>(bufA, bufB);       // l2
    acc3_kernel<<<elem_blocks, TB>>>(node_emb, bufA, bufB);
    spmm_csr_kernel<<<row_blocks, TB>>>(bufB, bufA);       // l3 (overwrites bufA)

    final_kernel<<<pair_blocks, TB>>>(bufA, user_ids, item_ids, out, n_pairs);
}

// round 7
// speedup vs baseline: 2.2114x; 1.3775x over previous
#include <cuda_runtime.h>
#include <cstdint>

#define NUM_USERS  100000
#define NUM_ITEMS  50000
#define N_TOTAL    150100
#define EMBED_DIM  64
#define VEC_PER_ROW (EMBED_DIM / 4)            // 16 float4 per node row
#define N4_TOTAL   (N_TOTAL * VEC_PER_ROW)
#define MAX_EDGES  3000000

// ---------------- device scratch (no runtime allocation) -------------------
__device__ int    g_count  [N_TOTAL];
__device__ int    g_offsets[N_TOTAL];
__device__ int    g_rank   [MAX_EDGES];
__device__ int2   g_pedge  [MAX_EDGES];        // {col, val-bits}, row-grouped
__device__ float4 g_bufA[N4_TOTAL];            // layer-1 output
__device__ float4 g_bufB[N4_TOTAL];            // layer-2 output

// ---------------------------------------------------------------------------
__global__ void zero_count_kernel() {
    int i = blockIdx.x * blockDim.x + threadIdx.x;
    if (i < N_TOTAL) g_count[i] = 0;
}

// Histogram; the atomic return value IS the edge's rank within its row.
// 4 edges/thread, vectorized row load + rank store.
__global__ void hist_kernel(const int* __restrict__ adj_row, int n_edges) {
    int i = blockIdx.x * blockDim.x + threadIdx.x;
    int e = i * 4;
    if (e + 3 < n_edges) {
        int4 r = *(const int4*)(adj_row + e);
        int4 k;
        k.x = atomicAdd(&g_count[r.x], 1);
        k.y = atomicAdd(&g_count[r.y], 1);
        k.z = atomicAdd(&g_count[r.z], 1);
        k.w = atomicAdd(&g_count[r.w], 1);
        *(int4*)(g_rank + e) = k;
    } else if (e < n_edges) {
        for (int q = e; q < n_edges; q++)
            g_rank[q] = atomicAdd(&g_count[adj_row[q]], 1);
    }
}

// Single-block exclusive scan over g_count -> g_offsets.
#define SCAN_T 1024
__global__ void scan_kernel() {
    __shared__ int wsum[32];
    __shared__ int s_carry;
    int tid = threadIdx.x;
    if (tid == 0) s_carry = 0;
    __syncthreads();

    const int CHUNK = SCAN_T * 4;
    for (int base = 0; base < N_TOTAL; base += CHUNK) {
        int idx = base + tid * 4;
        int a[4]; int sum = 0;
        #pragma unroll
        for (int k = 0; k < 4; k++) {
            int i = idx + k;
            a[k] = (i < N_TOTAL) ? g_count[i] : 0;
            sum += a[k];
        }
        int v = sum;
        #pragma unroll
        for (int off = 1; off < 32; off <<= 1) {
            int n = __shfl_up_sync(0xffffffffu, v, off);
            if ((tid & 31) >= off) v += n;
        }
        if ((tid & 31) == 31) wsum[tid >> 5] = v;
        __syncthreads();
        if (tid < 32) {
            int w = wsum[tid];
            #pragma unroll
            for (int off = 1; off < 32; off <<= 1) {
                int n = __shfl_up_sync(0xffffffffu, w, off);
                if (tid >= off) w += n;
            }
            wsum[tid] = w;
        }
        __syncthreads();
        int incl = v + ((tid >= 32) ? wsum[(tid >> 5) - 1] : 0);
        int run  = s_carry + incl - sum;
        #pragma unroll
        for (int k = 0; k < 4; k++) {
            int i = idx + k;
            if (i < N_TOTAL) g_offsets[i] = run;
            run += a[k];
        }
        __syncthreads();
        if (tid == SCAN_T - 1) s_carry += incl;
        __syncthreads();
    }
}

// Atomic-free permute: p = offsets[row] + rank[e]. 4 edges/thread.
__global__ void fill_kernel(const int* __restrict__ adj_row,
                            const int* __restrict__ adj_col,
                            const float* __restrict__ adj_val,
                            int n_edges) {
    int i = blockIdx.x * blockDim.x + threadIdx.x;
    int e = i * 4;
    if (e + 3 < n_edges) {
        int4   r = *(const int4*)(adj_row + e);
        int4   k = *(const int4*)(g_rank  + e);
        int4   c = *(const int4*)(adj_col + e);
        float4 v = *(const float4*)(adj_val + e);
        g_pedge[__ldg(&g_offsets[r.x]) + k.x] = make_int2(c.x, __float_as_int(v.x));
        g_pedge[__ldg(&g_offsets[r.y]) + k.y] = make_int2(c.y, __float_as_int(v.y));
        g_pedge[__ldg(&g_offsets[r.z]) + k.z] = make_int2(c.z, __float_as_int(v.z));
        g_pedge[__ldg(&g_offsets[r.w]) + k.w] = make_int2(c.w, __float_as_int(v.w));
    } else if (e < n_edges) {
        for (int q = e; q < n_edges; q++)
            g_pedge[g_offsets[adj_row[q]] + g_rank[q]] =
                make_int2(adj_col[q], __float_as_int(adj_val[q]));
    }
}

// ---------------------------------------------------------------------------
// CSR SpMM: 8 lanes per row, 2 float4 per lane, unroll 4 -> 8 outstanding
// gathers per thread. No atomics; one coalesced 256B write per row.
// ---------------------------------------------------------------------------
__global__ void spmm_csr_kernel(const float4* __restrict__ in,
                                float4* __restrict__ out) {
    int t    = blockIdx.x * blockDim.x + threadIdx.x;
    int r    = t >> 3;
    int lane = t & 7;
    if (r >= N_TOTAL) return;

    int beg = __ldg(&g_offsets[r]);
    int cnt = __ldg(&g_count[r]);

    float4 a0 = make_float4(0.f,0.f,0.f,0.f);
    float4 a1 = make_float4(0.f,0.f,0.f,0.f);

    int j = 0;
    for (; j + 3 < cnt; j += 4) {
        int2 e0 = __ldg(&g_pedge[beg + j]);
        int2 e1 = __ldg(&g_pedge[beg + j + 1]);
        int2 e2 = __ldg(&g_pedge[beg + j + 2]);
        int2 e3 = __ldg(&g_pedge[beg + j + 3]);
        const float4* p0 = in + (long long)e0.x * VEC_PER_ROW + lane;
        const float4* p1 = in + (long long)e1.x * VEC_PER_ROW + lane;
        const float4* p2 = in + (long long)e2.x * VEC_PER_ROW + lane;
        const float4* p3 = in + (long long)e3.x * VEC_PER_ROW + lane;
        float4 x0 = __ldg(p0), y0 = __ldg(p0 + 8);
        float4 x1 = __ldg(p1), y1 = __ldg(p1 + 8);
        float4 x2 = __ldg(p2), y2 = __ldg(p2 + 8);
        float4 x3 = __ldg(p3), y3 = __ldg(p3 + 8);
        float v0 = __int_as_float(e0.y), v1 = __int_as_float(e1.y);
        float v2 = __int_as_float(e2.y), v3 = __int_as_float(e3.y);
        a0.x += v0*x0.x; a0.y += v0*x0.y; a0.z += v0*x0.z; a0.w += v0*x0.w;
        a1.x += v0*y0.x; a1.y += v0*y0.y; a1.z += v0*y0.z; a1.w += v0*y0.w;
        a0.x += v1*x1.x; a0.y += v1*x1.y; a0.z += v1*x1.z; a0.w += v1*x1.w;
        a1.x += v1*y1.x; a1.y += v1*y1.y; a1.z += v1*y1.z; a1.w += v1*y1.w;
        a0.x += v2*x2.x; a0.y += v2*x2.y; a0.z += v2*x2.z; a0.w += v2*x2.w;
        a1.x += v2*y2.x; a1.y += v2*y2.y; a1.z += v2*y2.z; a1.w += v2*y2.w;
        a0.x += v3*x3.x; a0.y += v3*x3.y; a0.z += v3*x3.z; a0.w += v3*x3.w;
        a1.x += v3*y3.x; a1.y += v3*y3.y; a1.z += v3*y3.z; a1.w += v3*y3.w;
    }
    for (; j < cnt; j++) {
        int2 e0 = __ldg(&g_pedge[beg + j]);
        const float4* p0 = in + (long long)e0.x * VEC_PER_ROW + lane;
        float4 x0 = __ldg(p0), y0 = __ldg(p0 + 8);
        float v0 = __int_as_float(e0.y);
        a0.x += v0*x0.x; a0.y += v0*x0.y; a0.z += v0*x0.z; a0.w += v0*x0.w;
        a1.x += v0*y0.x; a1.y += v0*y0.y; a1.z += v0*y0.z; a1.w += v0*y0.w;
    }
    out[(long long)r * VEC_PER_ROW + lane]     = a0;
    out[(long long)r * VEC_PER_ROW + lane + 8] = a1;
}

// ---------------------------------------------------------------------------
// Fused layer-3 + accumulate + dot, only at the 8192 sampled rows.
// One warp per pair: lanes 0-15 user row, lanes 16-31 item row.
// acc_lane = emb + l1 + l2 + (l3 gathered from l2); dot via half-warp swap.
// ---------------------------------------------------------------------------
__global__ void final_kernel(const float4* __restrict__ emb,
                             const float4* __restrict__ l1,
                             const float4* __restrict__ l2,
                             const int* __restrict__ user_ids,
                             const int* __restrict__ item_ids,
                             float* __restrict__ out,
                             int n_pairs) {
    int t    = blockIdx.x * blockDim.x + threadIdx.x;
    int p    = t >> 5;
    int lane = t & 31;
    if (p >= n_pairs) return;

    int half = lane >> 4;          // 0 = user, 1 = item
    int sl   = lane & 15;
    int row  = half ? (NUM_USERS + __ldg(item_ids + p)) : __ldg(user_ids + p);

    long long off = (long long)row * VEC_PER_ROW + sl;
    float4 e4 = __ldg(emb + off);
    float4 a4 = __ldg(l1  + off);
    float4 b4 = __ldg(l2  + off);

    float4 acc = make_float4(e4.x + a4.x + b4.x,
                             e4.y + a4.y + b4.y,
                             e4.z + a4.z + b4.z,
                             e4.w + a4.w + b4.w);

    // layer-3 gather for this row
    int beg = __ldg(&g_offsets[row]);
    int cnt = __ldg(&g_count[row]);
    float4 l3 = make_float4(0.f,0.f,0.f,0.f);
    int j = 0;
    for (; j + 1 < cnt; j += 2) {
        int2 ed0 = __ldg(&g_pedge[beg + j]);
        int2 ed1 = __ldg(&g_pedge[beg + j + 1]);
        float4 x0 = __ldg(l2 + (long long)ed0.x * VEC_PER_ROW + sl);
        float4 x1 = __ldg(l2 + (long long)ed1.x * VEC_PER_ROW + sl);
        float v0 = __int_as_float(ed0.y), v1 = __int_as_float(ed1.y);
        l3.x += v0*x0.x + v1*x1.x; l3.y += v0*x0.y + v1*x1.y;
        l3.z += v0*x0.z + v1*x1.z; l3.w += v0*x0.w + v1*x1.w;
    }
    if (j < cnt) {
        int2 ed0 = __ldg(&g_pedge[beg + j]);
        float4 x0 = __ldg(l2 + (long long)ed0.x * VEC_PER_ROW + sl);
        float v0 = __int_as_float(ed0.y);
        l3.x += v0*x0.x; l3.y += v0*x0.y; l3.z += v0*x0.z; l3.w += v0*x0.w;
    }

    acc.x = (acc.x + l3.x) * 0.25f;
    acc.y = (acc.y + l3.y) * 0.25f;
    acc.z = (acc.z + l3.z) * 0.25f;
    acc.w = (acc.w + l3.w) * 0.25f;

    // swap halves: lane L gets the other row's lane-L vector
    float4 oth;
    oth.x = __shfl_xor_sync(0xffffffffu, acc.x, 16);
    oth.y = __shfl_xor_sync(0xffffffffu, acc.y, 16);
    oth.z = __shfl_xor_sync(0xffffffffu, acc.z, 16);
    oth.w = __shfl_xor_sync(0xffffffffu, acc.w, 16);

    float partial = acc.x*oth.x + acc.y*oth.y + acc.z*oth.z + acc.w*oth.w;

    #pragma unroll
    for (int o = 8; o > 0; o >>= 1)
        partial += __shfl_down_sync(0xffffffffu, partial, o);

    if (lane == 0) out[p] = partial;
}

// ---------------------------------------------------------------------------
extern "C" void kernel_launch(void* const* d_in, const int* in_sizes, int n_in,
                              void* d_out, int out_size) {
    const float4* node_emb = (const float4*)d_in[0];
    const float*  adj_val  = (const float*)d_in[1];
    const int*    adj_row  = (const int*)d_in[2];
    const int*    adj_col  = (const int*)d_in[3];
    const int*    user_ids = (const int*)d_in[4];
    const int*    item_ids = (const int*)d_in[5];
    float*        out      = (float*)d_out;

    int n_edges = in_sizes[1];
    int n_pairs = out_size;

    float4 *bufA, *bufB;
    cudaGetSymbolAddress((void**)&bufA, g_bufA);
    cudaGetSymbolAddress((void**)&bufB, g_bufB);

    const int TB = 256;
    int node_blocks  = (N_TOTAL + TB - 1) / TB;
    int edge4_blocks = ((n_edges + 3) / 4 + TB - 1) / TB;
    int row_blocks   = (N_TOTAL * 8 + TB - 1) / TB;
    int pair_blocks  = (n_pairs * 32 + TB - 1) / TB;

    // --- CSR build ---
    zero_count_kernel<<<node_blocks, TB>>>();
    hist_kernel<<<edge4_blocks, TB>>>(adj_row, n_edges);
    scan_kernel<<<1, SCAN_T>>>();
    fill_kernel<<<edge4_blocks, TB>>>(adj_row, adj_col, adj_val, n_edges);

    // --- 2 full propagation layers ---
    spmm_csr_kernel<<<row_blocks, TB>>>(node_emb, bufA);   // l1
    spmm_csr_kernel<<<row_blocks, TB>>>(bufA, bufB);       // l2

    // --- fused l3 + acc + dot at the 8192 sampled rows only ---
    final_kernel<<<pair_blocks, TB>>>(node_emb, bufA, bufB,
                                      user_ids, item_ids, out, n_pairs);
}

// round 8
// speedup vs baseline: 3.1197x; 1.4108x over previous
#include <cuda_runtime.h>
#include <cuda_fp16.h>
#include <cstdint>

#define NUM_USERS  100000
#define NUM_ITEMS  50000
#define N_TOTAL    150100
#define EMBED_DIM  64
#define VEC_PER_ROW 16                     // float4 per fp32 node row
#define U4_PER_ROW  8                      // uint4 (8 halves) per half node row
#define U2_PER_ROW  16                     // uint2 (4 halves) per half node row
#define MAX_EDGES  3000000

#define SCAN_T      1024
#define SCAN_CHUNK  4096                   // SCAN_T * 4
#define SCAN_NBLK   37                     // ceil(N_TOTAL / 4096)

// ---------------- device scratch (no runtime allocation) -------------------
__device__ int    g_count  [N_TOTAL];
__device__ int    g_offsets[N_TOTAL];      // block-local exclusive prefix
__device__ int    g_bsum   [SCAN_NBLK];    // per-scan-block exclusive base
__device__ int    g_rank   [MAX_EDGES];
__device__ int2   g_pedge  [MAX_EDGES];    // {col, val-bits}, row-grouped
__device__ uint4  g_embh[N_TOTAL * U4_PER_ROW];   // node_emb in half
__device__ uint4  g_l1h [N_TOTAL * U4_PER_ROW];   // layer-1 (half)
__device__ uint4  g_l2h [N_TOTAL * U4_PER_ROW];   // layer-2 (half)

// ---------------------------------------------------------------------------
__global__ void zero_count_kernel() {
    int i = blockIdx.x * blockDim.x + threadIdx.x;
    if (i < N_TOTAL) g_count[i] = 0;
}

// fp32 -> fp16 conversion of node_emb. One thread = 8 floats -> 1 uint4.
__global__ void convert_kernel(const float4* __restrict__ emb) {
    int i = blockIdx.x * blockDim.x + threadIdx.x;
    if (i >= N_TOTAL * U4_PER_ROW) return;
    float4 a = __ldg(emb + 2 * i);
    float4 b = __ldg(emb + 2 * i + 1);
    __half2 h0 = __floats2half2_rn(a.x, a.y);
    __half2 h1 = __floats2half2_rn(a.z, a.w);
    __half2 h2 = __floats2half2_rn(b.x, b.y);
    __half2 h3 = __floats2half2_rn(b.z, b.w);
    uint4 o;
    o.x = *reinterpret_cast<uint32_t*>(&h0);
    o.y = *reinterpret_cast<uint32_t*>(&h1);
    o.z = *reinterpret_cast<uint32_t*>(&h2);
    o.w = *reinterpret_cast<uint32_t*>(&h3);
    g_embh[i] = o;
}

// Histogram; atomic return value = edge's rank within its row. 8 edges/thread.
__global__ void hist_kernel(const int* __restrict__ adj_row, int n_edges) {
    int i = blockIdx.x * blockDim.x + threadIdx.x;
    int e = i * 8;
    if (e + 7 < n_edges) {
        int4 r0 = *(const int4*)(adj_row + e);
        int4 r1 = *(const int4*)(adj_row + e + 4);
        int4 k0, k1;
        k0.x = atomicAdd(&g_count[r0.x], 1);
        k0.y = atomicAdd(&g_count[r0.y], 1);
        k0.z = atomicAdd(&g_count[r0.z], 1);
        k0.w = atomicAdd(&g_count[r0.w], 1);
        k1.x = atomicAdd(&g_count[r1.x], 1);
        k1.y = atomicAdd(&g_count[r1.y], 1);
        k1.z = atomicAdd(&g_count[r1.z], 1);
        k1.w = atomicAdd(&g_count[r1.w], 1);
        *(int4*)(g_rank + e)     = k0;
        *(int4*)(g_rank + e + 4) = k1;
    } else if (e < n_edges) {
        for (int q = e; q < n_edges; q++)
            g_rank[q] = atomicAdd(&g_count[adj_row[q]], 1);
    }
}

// Block-local exclusive scan over a 4096-element chunk of g_count.
__global__ void scan1_kernel() {
    __shared__ int wsum[32];
    int tid  = threadIdx.x;
    int base = blockIdx.x * SCAN_CHUNK;
    int idx  = base + tid * 4;

    int a[4]; int sum = 0;
    #pragma unroll
    for (int k = 0; k < 4; k++) {
        int i = idx + k;
        a[k] = (i < N_TOTAL) ? g_count[i] : 0;
        sum += a[k];
    }
    int v = sum;
    #pragma unroll
    for (int off = 1; off < 32; off <<= 1) {
        int n = __shfl_up_sync(0xffffffffu, v, off);
        if ((tid & 31) >= off) v += n;
    }
    if ((tid & 31) == 31) wsum[tid >> 5] = v;
    __syncthreads();
    if (tid < 32) {
        int w = wsum[tid];
        #pragma unroll
        for (int off = 1; off < 32; off <<= 1) {
            int n = __shfl_up_sync(0xffffffffu, w, off);
            if (tid >= off) w += n;
        }
        wsum[tid] = w;
    }
    __syncthreads();
    int incl = v + ((tid >= 32) ? wsum[(tid >> 5) - 1] : 0);
    int run  = incl - sum;                 // block-local exclusive base
    #pragma unroll
    for (int k = 0; k < 4; k++) {
        int i = idx + k;
        if (i < N_TOTAL) g_offsets[i] = run;
        run += a[k];
    }
    if (tid == 0) g_bsum[blockIdx.x] = wsum[31];   // block total
}

// Exclusive scan of the 37 block totals (single 64-thread block).
__global__ void scan2_kernel() {
    __shared__ int w0tot;
    int tid = threadIdx.x;
    int v = (tid < SCAN_NBLK) ? g_bsum[tid] : 0;
    int x = v;
    #pragma unroll
    for (int off = 1; off < 32; off <<= 1) {
        int n = __shfl_up_sync(0xffffffffu, x, off);
        if ((tid & 31) >= off) x += n;
    }
    if (tid == 31) w0tot = x;
    __syncthreads();
    if (tid >= 32) x += w0tot;
    if (tid < SCAN_NBLK) g_bsum[tid] = x - v;      // exclusive
}

__device__ __forceinline__ int row_base(int r) {
    return __ldg(&g_offsets[r]) + __ldg(&g_bsum[r >> 12]);
}

// Atomic-free permute: p = base(row) + rank[e]. 8 edges/thread.
__global__ void fill_kernel(const int* __restrict__ adj_row,
                            const int* __restrict__ adj_col,
                            const float* __restrict__ adj_val,
                            int n_edges) {
    int i = blockIdx.x * blockDim.x + threadIdx.x;
    int e = i * 8;
    if (e + 7 < n_edges) {
        int4   r0 = *(const int4*)(adj_row + e);
        int4   r1 = *(const int4*)(adj_row + e + 4);
        int4   k0 = *(const int4*)(g_rank  + e);
        int4   k1 = *(const int4*)(g_rank  + e + 4);
        int4   c0 = *(const int4*)(adj_col + e);
        int4   c1 = *(const int4*)(adj_col + e + 4);
        float4 v0 = *(const float4*)(adj_val + e);
        float4 v1 = *(const float4*)(adj_val + e + 4);
        g_pedge[row_base(r0.x) + k0.x] = make_int2(c0.x, __float_as_int(v0.x));
        g_pedge[row_base(r0.y) + k0.y] = make_int2(c0.y, __float_as_int(v0.y));
        g_pedge[row_base(r0.z) + k0.z] = make_int2(c0.z, __float_as_int(v0.z));
        g_pedge[row_base(r0.w) + k0.w] = make_int2(c0.w, __float_as_int(v0.w));
        g_pedge[row_base(r1.x) + k1.x] = make_int2(c1.x, __float_as_int(v1.x));
        g_pedge[row_base(r1.y) + k1.y] = make_int2(c1.y, __float_as_int(v1.y));
        g_pedge[row_base(r1.z) + k1.z] = make_int2(c1.z, __float_as_int(v1.z));
        g_pedge[row_base(r1.w) + k1.w] = make_int2(c1.w, __float_as_int(v1.w));
    } else if (e < n_edges) {
        for (int q = e; q < n_edges; q++)
            g_pedge[row_base(adj_row[q]) + g_rank[q]] =
                make_int2(adj_col[q], __float_as_int(adj_val[q]));
    }
}

// ---------------------------------------------------------------------------
// CSR SpMM in half: 8 lanes/row, lane owns 8 halves (uint4 = 16B).
// Gather 128B/edge (one wavefront), fp32 accumulation, half output.
// ---------------------------------------------------------------------------
__device__ __forceinline__ void fma_h8(float2 acc[4], uint4 x, float v) {
    const __half2* h = reinterpret_cast<const __half2*>(&x);
    #pragma unroll
    for (int k = 0; k < 4; k++) {
        float2 f = __half22float2(h[k]);
        acc[k].x += v * f.x;
        acc[k].y += v * f.y;
    }
}

__global__ void spmm_half_kernel(const uint4* __restrict__ in,
                                 uint4* __restrict__ out) {
    int t    = blockIdx.x * blockDim.x + threadIdx.x;
    int r    = t >> 3;
    int lane = t & 7;
    if (r >= N_TOTAL) return;

    int beg = row_base(r);
    int cnt = __ldg(&g_count[r]);

    float2 acc[4];
    #pragma unroll
    for (int k = 0; k < 4; k++) acc[k] = make_float2(0.f, 0.f);

    int j = 0;
    for (; j + 3 < cnt; j += 4) {
        int2 e0 = __ldg(&g_pedge[beg + j]);
        int2 e1 = __ldg(&g_pedge[beg + j + 1]);
        int2 e2 = __ldg(&g_pedge[beg + j + 2]);
        int2 e3 = __ldg(&g_pedge[beg + j + 3]);
        uint4 x0 = __ldg(in + (long long)e0.x * U4_PER_ROW + lane);
        uint4 x1 = __ldg(in + (long long)e1.x * U4_PER_ROW + lane);
        uint4 x2 = __ldg(in + (long long)e2.x * U4_PER_ROW + lane);
        uint4 x3 = __ldg(in + (long long)e3.x * U4_PER_ROW + lane);
        fma_h8(acc, x0, __int_as_float(e0.y));
        fma_h8(acc, x1, __int_as_float(e1.y));
        fma_h8(acc, x2, __int_as_float(e2.y));
        fma_h8(acc, x3, __int_as_float(e3.y));
    }
    for (; j < cnt; j++) {
        int2 e0 = __ldg(&g_pedge[beg + j]);
        uint4 x0 = __ldg(in + (long long)e0.x * U4_PER_ROW + lane);
        fma_h8(acc, x0, __int_as_float(e0.y));
    }

    __half2 o0 = __floats2half2_rn(acc[0].x, acc[0].y);
    __half2 o1 = __floats2half2_rn(acc[1].x, acc[1].y);
    __half2 o2 = __floats2half2_rn(acc[2].x, acc[2].y);
    __half2 o3 = __floats2half2_rn(acc[3].x, acc[3].y);
    uint4 o;
    o.x = *reinterpret_cast<uint32_t*>(&o0);
    o.y = *reinterpret_cast<uint32_t*>(&o1);
    o.z = *reinterpret_cast<uint32_t*>(&o2);
    o.w = *reinterpret_cast<uint32_t*>(&o3);
    out[(long long)r * U4_PER_ROW + lane] = o;
}

// ---------------------------------------------------------------------------
// Fused layer-3 + accumulate + dot at the sampled rows.
// One warp per pair: lanes 0-15 user row, lanes 16-31 item row.
// Each lane owns 4 dims: emb fp32 (float4), l1/l2 half (uint2), l3 gathered.
// ---------------------------------------------------------------------------
__global__ void final_kernel(const float4* __restrict__ emb,
                             const int* __restrict__ user_ids,
                             const int* __restrict__ item_ids,
                             float* __restrict__ out,
                             int n_pairs) {
    int t    = blockIdx.x * blockDim.x + threadIdx.x;
    int p    = t >> 5;
    int lane = t & 31;
    if (p >= n_pairs) return;

    int half_ = lane >> 4;                  // 0 = user, 1 = item
    int sl    = lane & 15;
    int row   = half_ ? (NUM_USERS + __ldg(item_ids + p)) : __ldg(user_ids + p);

    const uint2* l1u = reinterpret_cast<const uint2*>(g_l1h);
    const uint2* l2u = reinterpret_cast<const uint2*>(g_l2h);

    long long off = (long long)row * U2_PER_ROW + sl;   // == row*16+sl, matches emb float4 idx
    float4 e4 = __ldg(emb + off);

    uint2 u1 = __ldg(l1u + off);
    uint2 u2 = __ldg(l2u + off);
    const __half2* h1 = reinterpret_cast<const __half2*>(&u1);
    const __half2* h2 = reinterpret_cast<const __half2*>(&u2);
    float2 a0 = __half22float2(h1[0]), a1 = __half22float2(h1[1]);
    float2 b0 = __half22float2(h2[0]), b1 = __half22float2(h2[1]);

    float4 acc = make_float4(e4.x + a0.x + b0.x,
                             e4.y + a0.y + b0.y,
                             e4.z + a1.x + b1.x,
                             e4.w + a1.y + b1.y);

    // layer-3 gather (from l2 half) for this row
    int beg = row_base(row);
    int cnt = __ldg(&g_count[row]);
    float4 l3 = make_float4(0.f, 0.f, 0.f, 0.f);
    int j = 0;
    for (; j + 1 < cnt; j += 2) {
        int2 ed0 = __ldg(&g_pedge[beg + j]);
        int2 ed1 = __ldg(&g_pedge[beg + j + 1]);
        uint2 x0 = __ldg(l2u + (long long)ed0.x * U2_PER_ROW + sl);
        uint2 x1 = __ldg(l2u + (long long)ed1.x * U2_PER_ROW + sl);
        float v0 = __int_as_float(ed0.y), v1 = __int_as_float(ed1.y);
        const __half2* p0 = reinterpret_cast<const __half2*>(&x0);
        const __half2* p1 = reinterpret_cast<const __half2*>(&x1);
        float2 f00 = __half22float2(p0[0]), f01 = __half22float2(p0[1]);
        float2 f10 = __half22float2(p1[0]), f11 = __half22float2(p1[1]);
        l3.x += v0 * f00.x + v1 * f10.x;
        l3.y += v0 * f00.y + v1 * f10.y;
        l3.z += v0 * f01.x + v1 * f11.x;
        l3.w += v0 * f01.y + v1 * f11.y;
    }
    if (j < cnt) {
        int2 ed0 = __ldg(&g_pedge[beg + j]);
        uint2 x0 = __ldg(l2u + (long long)ed0.x * U2_PER_ROW + sl);
        float v0 = __int_as_float(ed0.y);
        const __half2* p0 = reinterpret_cast<const __half2*>(&x0);
        float2 f00 = __half22float2(p0[0]), f01 = __half22float2(p0[1]);
        l3.x += v0 * f00.x; l3.y += v0 * f00.y;
        l3.z += v0 * f01.x; l3.w += v0 * f01.y;
    }

    acc.x = (acc.x + l3.x) * 0.25f;
    acc.y = (acc.y + l3.y) * 0.25f;
    acc.z = (acc.z + l3.z) * 0.25f;
    acc.w = (acc.w + l3.w) * 0.25f;

    float4 oth;
    oth.x = __shfl_xor_sync(0xffffffffu, acc.x, 16);
    oth.y = __shfl_xor_sync(0xffffffffu, acc.y, 16);
    oth.z = __shfl_xor_sync(0xffffffffu, acc.z, 16);
    oth.w = __shfl_xor_sync(0xffffffffu, acc.w, 16);

    float partial = acc.x*oth.x + acc.y*oth.y + acc.z*oth.z + acc.w*oth.w;

    #pragma unroll
    for (int o = 8; o > 0; o >>= 1)
        partial += __shfl_down_sync(0xffffffffu, partial, o);

    if (lane == 0) out[p] = partial;
}

// ---------------------------------------------------------------------------
extern "C" void kernel_launch(void* const* d_in, const int* in_sizes, int n_in,
                              void* d_out, int out_size) {
    const float4* node_emb = (const float4*)d_in[0];
    const float*  adj_val  = (const float*)d_in[1];
    const int*    adj_row  = (const int*)d_in[2];
    const int*    adj_col  = (const int*)d_in[3];
    const int*    user_ids = (const int*)d_in[4];
    const int*    item_ids = (const int*)d_in[5];
    float*        out      = (float*)d_out;

    int n_edges = in_sizes[1];
    int n_pairs = out_size;

    uint4 *embh, *l1h, *l2h;
    cudaGetSymbolAddress((void**)&embh, g_embh);
    cudaGetSymbolAddress((void**)&l1h,  g_l1h);
    cudaGetSymbolAddress((void**)&l2h,  g_l2h);

    const int TB = 256;
    int node_blocks  = (N_TOTAL + TB - 1) / TB;
    int conv_blocks  = (N_TOTAL * U4_PER_ROW + TB - 1) / TB;
    int edge8_blocks = ((n_edges + 7) / 8 + TB - 1) / TB;
    int row_blocks   = (N_TOTAL * 8 + TB - 1) / TB;
    int pair_blocks  = (n_pairs * 32 + TB - 1) / TB;

    // --- CSR build + half conversion ---
    zero_count_kernel<<<node_blocks, TB>>>();
    convert_kernel<<<conv_blocks, TB>>>(node_emb);
    hist_kernel<<<edge8_blocks, TB>>>(adj_row, n_edges);
    scan1_kernel<<<SCAN_NBLK, SCAN_T>>>();
    scan2_kernel<<<1, 64>>>();
    fill_kernel<<<edge8_blocks, TB>>>(adj_row, adj_col, adj_val, n_edges);

    // --- 2 full propagation layers in half ---
    spmm_half_kernel<<<row_blocks, TB>>>(embh, l1h);    // l1
    spmm_half_kernel<<<row_blocks, TB>>>(l1h,  l2h);    // l2

    // --- fused l3 + acc + dot at the sampled rows only ---
    final_kernel<<<pair_blocks, TB>>>(node_emb, user_ids, item_ids, out, n_pairs);
}

// round 9
// speedup vs baseline: 3.2220x; 1.0328x over previous
#include <cuda_runtime.h>
#include <cuda_fp16.h>
#include <cstdint>

#define NUM_USERS  100000
#define NUM_ITEMS  50000
#define N_TOTAL    150100
#define EMBED_DIM  64
#define VEC_PER_ROW 16                     // float4 per fp32 node row
#define U4_PER_ROW  8                      // uint4 (8 halves) per half node row
#define U2_PER_ROW  16                     // uint2 (4 halves) per half node row
#define MAX_EDGES  3000000

#define SCAN_T      1024
#define SCAN_CHUNK  4096                   // SCAN_T * 4
#define SCAN_NBLK   37                     // ceil(N_TOTAL / 4096)

// ---------------- device scratch (no runtime allocation) -------------------
__device__ int    g_count  [N_TOTAL];
__device__ int    g_offsets[N_TOTAL];      // block-local exclusive prefix
__device__ int    g_bsum   [SCAN_NBLK];    // per-scan-block exclusive base
__device__ int    g_rank   [MAX_EDGES];
__device__ int2   g_pedge  [MAX_EDGES];    // {col, val-bits}, row-grouped
__device__ uint4  g_embh[N_TOTAL * U4_PER_ROW];   // node_emb in half
__device__ uint4  g_l1h [N_TOTAL * U4_PER_ROW];   // layer-1 (half)
__device__ uint4  g_l2h [N_TOTAL * U4_PER_ROW];   // layer-2 (half)

// ---------------------------------------------------------------------------
// Fused: zero g_count + convert node_emb fp32 -> fp16.
// Grid covers N_TOTAL * U4_PER_ROW threads; first N_TOTAL also zero a counter.
// ---------------------------------------------------------------------------
__global__ void init_kernel(const float4* __restrict__ emb) {
    int i = blockIdx.x * blockDim.x + threadIdx.x;
    if (i < N_TOTAL) g_count[i] = 0;
    if (i >= N_TOTAL * U4_PER_ROW) return;
    float4 a = __ldg(emb + 2 * i);
    float4 b = __ldg(emb + 2 * i + 1);
    __half2 h0 = __floats2half2_rn(a.x, a.y);
    __half2 h1 = __floats2half2_rn(a.z, a.w);
    __half2 h2 = __floats2half2_rn(b.x, b.y);
    __half2 h3 = __floats2half2_rn(b.z, b.w);
    uint4 o;
    o.x = *reinterpret_cast<uint32_t*>(&h0);
    o.y = *reinterpret_cast<uint32_t*>(&h1);
    o.z = *reinterpret_cast<uint32_t*>(&h2);
    o.w = *reinterpret_cast<uint32_t*>(&h3);
    g_embh[i] = o;
}

// Histogram; atomic return value = edge's rank within its row. 16 edges/thread.
__global__ void __launch_bounds__(256) hist_kernel(const int* __restrict__ adj_row,
                                                   int n_edges) {
    int i = blockIdx.x * blockDim.x + threadIdx.x;
    int e = i * 16;
    if (e + 15 < n_edges) {
        #pragma unroll
        for (int g = 0; g < 4; g++) {
            int4 r = *(const int4*)(adj_row + e + g * 4);
            int4 k;
            k.x = atomicAdd(&g_count[r.x], 1);
            k.y = atomicAdd(&g_count[r.y], 1);
            k.z = atomicAdd(&g_count[r.z], 1);
            k.w = atomicAdd(&g_count[r.w], 1);
            *(int4*)(g_rank + e + g * 4) = k;
        }
    } else if (e < n_edges) {
        for (int q = e; q < n_edges; q++)
            g_rank[q] = atomicAdd(&g_count[adj_row[q]], 1);
    }
}

// Block-local exclusive scan over a 4096-element chunk of g_count.
__global__ void scan1_kernel() {
    __shared__ int wsum[32];
    int tid  = threadIdx.x;
    int base = blockIdx.x * SCAN_CHUNK;
    int idx  = base + tid * 4;

    int a[4]; int sum = 0;
    #pragma unroll
    for (int k = 0; k < 4; k++) {
        int i = idx + k;
        a[k] = (i < N_TOTAL) ? g_count[i] : 0;
        sum += a[k];
    }
    int v = sum;
    #pragma unroll
    for (int off = 1; off < 32; off <<= 1) {
        int n = __shfl_up_sync(0xffffffffu, v, off);
        if ((tid & 31) >= off) v += n;
    }
    if ((tid & 31) == 31) wsum[tid >> 5] = v;
    __syncthreads();
    if (tid < 32) {
        int w = wsum[tid];
        #pragma unroll
        for (int off = 1; off < 32; off <<= 1) {
            int n = __shfl_up_sync(0xffffffffu, w, off);
            if (tid >= off) w += n;
        }
        wsum[tid] = w;
    }
    __syncthreads();
    int incl = v + ((tid >= 32) ? wsum[(tid >> 5) - 1] : 0);
    int run  = incl - sum;                 // block-local exclusive base
    #pragma unroll
    for (int k = 0; k < 4; k++) {
        int i = idx + k;
        if (i < N_TOTAL) g_offsets[i] = run;
        run += a[k];
    }
    if (tid == 0) g_bsum[blockIdx.x] = wsum[31];   // block total
}

// Exclusive scan of the 37 block totals (single 64-thread block).
__global__ void scan2_kernel() {
    __shared__ int w0tot;
    int tid = threadIdx.x;
    int v = (tid < SCAN_NBLK) ? g_bsum[tid] : 0;
    int x = v;
    #pragma unroll
    for (int off = 1; off < 32; off <<= 1) {
        int n = __shfl_up_sync(0xffffffffu, x, off);
        if ((tid & 31) >= off) x += n;
    }
    if (tid == 31) w0tot = x;
    __syncthreads();
    if (tid >= 32) x += w0tot;
    if (tid < SCAN_NBLK) g_bsum[tid] = x - v;      // exclusive
}

__device__ __forceinline__ int row_base(int r) {
    return __ldg(&g_offsets[r]) + __ldg(&g_bsum[r >> 12]);
}

// Atomic-free permute: p = base(row) + rank[e]. 16 edges/thread.
__global__ void __launch_bounds__(256) fill_kernel(const int* __restrict__ adj_row,
                                                   const int* __restrict__ adj_col,
                                                   const float* __restrict__ adj_val,
                                                   int n_edges) {
    int i = blockIdx.x * blockDim.x + threadIdx.x;
    int e = i * 16;
    if (e + 15 < n_edges) {
        #pragma unroll
        for (int g = 0; g < 4; g++) {
            int4   r = *(const int4*)(adj_row + e + g * 4);
            int4   k = *(const int4*)(g_rank  + e + g * 4);
            int4   c = *(const int4*)(adj_col + e + g * 4);
            float4 v = *(const float4*)(adj_val + e + g * 4);
            g_pedge[row_base(r.x) + k.x] = make_int2(c.x, __float_as_int(v.x));
            g_pedge[row_base(r.y) + k.y] = make_int2(c.y, __float_as_int(v.y));
            g_pedge[row_base(r.z) + k.z] = make_int2(c.z, __float_as_int(v.z));
            g_pedge[row_base(r.w) + k.w] = make_int2(c.w, __float_as_int(v.w));
        }
    } else if (e < n_edges) {
        for (int q = e; q < n_edges; q++)
            g_pedge[row_base(adj_row[q]) + g_rank[q]] =
                make_int2(adj_col[q], __float_as_int(adj_val[q]));
    }
}

// ---------------------------------------------------------------------------
// CSR SpMM in half: 8 lanes/row, lane owns 8 halves (uint4 = 16B).
// Software-pipelined: next 4 edge records load while current 4 gathers fly.
// fp32 accumulation, half output.
// ---------------------------------------------------------------------------
__device__ __forceinline__ void fma_h8(float2 acc[4], uint4 x, float v) {
    const __half2* h = reinterpret_cast<const __half2*>(&x);
    #pragma unroll
    for (int k = 0; k < 4; k++) {
        float2 f = __half22float2(h[k]);
        acc[k].x += v * f.x;
        acc[k].y += v * f.y;
    }
}

__global__ void __launch_bounds__(256) spmm_half_kernel(const uint4* __restrict__ in,
                                                        uint4* __restrict__ out) {
    int t    = blockIdx.x * blockDim.x + threadIdx.x;
    int r    = t >> 3;
    int lane = t & 7;
    if (r >= N_TOTAL) return;

    int beg = row_base(r);
    int cnt = __ldg(&g_count[r]);

    float2 acc[4];
    #pragma unroll
    for (int k = 0; k < 4; k++) acc[k] = make_float2(0.f, 0.f);

    int j = 0;
    int2 ea0, ea1, ea2, ea3;
    if (j + 3 < cnt) {
        ea0 = __ldg(&g_pedge[beg]);
        ea1 = __ldg(&g_pedge[beg + 1]);
        ea2 = __ldg(&g_pedge[beg + 2]);
        ea3 = __ldg(&g_pedge[beg + 3]);
    }
    while (j + 3 < cnt) {
        // gathers for the current 4 edges
        uint4 x0 = __ldg(in + (long long)ea0.x * U4_PER_ROW + lane);
        uint4 x1 = __ldg(in + (long long)ea1.x * U4_PER_ROW + lane);
        uint4 x2 = __ldg(in + (long long)ea2.x * U4_PER_ROW + lane);
        uint4 x3 = __ldg(in + (long long)ea3.x * U4_PER_ROW + lane);
        // prefetch the next 4 edge records (independent of the gathers)
        int jn = j + 4;
        int2 eb0, eb1, eb2, eb3;
        bool more = (jn + 3 < cnt);
        if (more) {
            eb0 = __ldg(&g_pedge[beg + jn]);
            eb1 = __ldg(&g_pedge[beg + jn + 1]);
            eb2 = __ldg(&g_pedge[beg + jn + 2]);
            eb3 = __ldg(&g_pedge[beg + jn + 3]);
        }
        fma_h8(acc, x0, __int_as_float(ea0.y));
        fma_h8(acc, x1, __int_as_float(ea1.y));
        fma_h8(acc, x2, __int_as_float(ea2.y));
        fma_h8(acc, x3, __int_as_float(ea3.y));
        ea0 = eb0; ea1 = eb1; ea2 = eb2; ea3 = eb3;
        j = jn;
    }
    for (; j < cnt; j++) {
        int2 e0 = __ldg(&g_pedge[beg + j]);
        uint4 x0 = __ldg(in + (long long)e0.x * U4_PER_ROW + lane);
        fma_h8(acc, x0, __int_as_float(e0.y));
    }

    __half2 o0 = __floats2half2_rn(acc[0].x, acc[0].y);
    __half2 o1 = __floats2half2_rn(acc[1].x, acc[1].y);
    __half2 o2 = __floats2half2_rn(acc[2].x, acc[2].y);
    __half2 o3 = __floats2half2_rn(acc[3].x, acc[3].y);
    uint4 o;
    o.x = *reinterpret_cast<uint32_t*>(&o0);
    o.y = *reinterpret_cast<uint32_t*>(&o1);
    o.z = *reinterpret_cast<uint32_t*>(&o2);
    o.w = *reinterpret_cast<uint32_t*>(&o3);
    out[(long long)r * U4_PER_ROW + lane] = o;
}

// ---------------------------------------------------------------------------
// Fused layer-3 + accumulate + dot at the sampled rows.
// One warp per pair: lanes 0-15 user row, lanes 16-31 item row.
// ---------------------------------------------------------------------------
__global__ void final_kernel(const float4* __restrict__ emb,
                             const int* __restrict__ user_ids,
                             const int* __restrict__ item_ids,
                             float* __restrict__ out,
                             int n_pairs) {
    int t    = blockIdx.x * blockDim.x + threadIdx.x;
    int p    = t >> 5;
    int lane = t & 31;
    if (p >= n_pairs) return;

    int half_ = lane >> 4;                  // 0 = user, 1 = item
    int sl    = lane & 15;
    int row   = half_ ? (NUM_USERS + __ldg(item_ids + p)) : __ldg(user_ids + p);

    const uint2* l1u = reinterpret_cast<const uint2*>(g_l1h);
    const uint2* l2u = reinterpret_cast<const uint2*>(g_l2h);

    long long off = (long long)row * U2_PER_ROW + sl;
    float4 e4 = __ldg(emb + off);

    uint2 u1 = __ldg(l1u + off);
    uint2 u2 = __ldg(l2u + off);
    const __half2* h1 = reinterpret_cast<const __half2*>(&u1);
    const __half2* h2 = reinterpret_cast<const __half2*>(&u2);
    float2 a0 = __half22float2(h1[0]), a1 = __half22float2(h1[1]);
    float2 b0 = __half22float2(h2[0]), b1 = __half22float2(h2[1]);

    float4 acc = make_float4(e4.x + a0.x + b0.x,
                             e4.y + a0.y + b0.y,
                             e4.z + a1.x + b1.x,
                             e4.w + a1.y + b1.y);

    // layer-3 gather (from l2 half) for this row
    int beg = row_base(row);
    int cnt = __ldg(&g_count[row]);
    float4 l3 = make_float4(0.f, 0.f, 0.f, 0.f);
    int j = 0;
    for (; j + 1 < cnt; j += 2) {
        int2 ed0 = __ldg(&g_pedge[beg + j]);
        int2 ed1 = __ldg(&g_pedge[beg + j + 1]);
        uint2 x0 = __ldg(l2u + (long long)ed0.x * U2_PER_ROW + sl);
        uint2 x1 = __ldg(l2u + (long long)ed1.x * U2_PER_ROW + sl);
        float v0 = __int_as_float(ed0.y), v1 = __int_as_float(ed1.y);
        const __half2* p0 = reinterpret_cast<const __half2*>(&x0);
        const __half2* p1 = reinterpret_cast<const __half2*>(&x1);
        float2 f00 = __half22float2(p0[0]), f01 = __half22float2(p0[1]);
        float2 f10 = __half22float2(p1[0]), f11 = __half22float2(p1[1]);
        l3.x += v0 * f00.x + v1 * f10.x;
        l3.y += v0 * f00.y + v1 * f10.y;
        l3.z += v0 * f01.x + v1 * f11.x;
        l3.w += v0 * f01.y + v1 * f11.y;
    }
    if (j < cnt) {
        int2 ed0 = __ldg(&g_pedge[beg + j]);
        uint2 x0 = __ldg(l2u + (long long)ed0.x * U2_PER_ROW + sl);
        float v0 = __int_as_float(ed0.y);
        const __half2* p0 = reinterpret_cast<const __half2*>(&x0);
        float2 f00 = __half22float2(p0[0]), f01 = __half22float2(p0[1]);
        l3.x += v0 * f00.x; l3.y += v0 * f00.y;
        l3.z += v0 * f01.x; l3.w += v0 * f01.y;
    }

    acc.x = (acc.x + l3.x) * 0.25f;
    acc.y = (acc.y + l3.y) * 0.25f;
    acc.z = (acc.z + l3.z) * 0.25f;
    acc.w = (acc.w + l3.w) * 0.25f;

    float4 oth;
    oth.x = __shfl_xor_sync(0xffffffffu, acc.x, 16);
    oth.y = __shfl_xor_sync(0xffffffffu, acc.y, 16);
    oth.z = __shfl_xor_sync(0xffffffffu, acc.z, 16);
    oth.w = __shfl_xor_sync(0xffffffffu, acc.w, 16);

    float partial = acc.x*oth.x + acc.y*oth.y + acc.z*oth.z + acc.w*oth.w;

    #pragma unroll
    for (int o = 8; o > 0; o >>= 1)
        partial += __shfl_down_sync(0xffffffffu, partial, o);

    if (lane == 0) out[p] = partial;
}

// ---------------------------------------------------------------------------
extern "C" void kernel_launch(void* const* d_in, const int* in_sizes, int n_in,
                              void* d_out, int out_size) {
    const float4* node_emb = (const float4*)d_in[0];
    const float*  adj_val  = (const float*)d_in[1];
    const int*    adj_row  = (const int*)d_in[2];
    const int*    adj_col  = (const int*)d_in[3];
    const int*    user_ids = (const int*)d_in[4];
    const int*    item_ids = (const int*)d_in[5];
    float*        out      = (float*)d_out;

    int n_edges = in_sizes[1];
    int n_pairs = out_size;

    uint4 *embh, *l1h, *l2h;
    cudaGetSymbolAddress((void**)&embh, g_embh);
    cudaGetSymbolAddress((void**)&l1h,  g_l1h);
    cudaGetSymbolAddress((void**)&l2h,  g_l2h);

    const int TB = 256;
    int init_blocks   = (N_TOTAL * U4_PER_ROW + TB - 1) / TB;
    int edge16_blocks = ((n_edges + 15) / 16 + TB - 1) / TB;
    int row_blocks    = (N_TOTAL * 8 + TB - 1) / TB;
    int pair_blocks   = (n_pairs * 32 + TB - 1) / TB;

    // --- CSR build + half conversion ---
    init_kernel<<<init_blocks, TB>>>(node_emb);
    hist_kernel<<<edge16_blocks, TB>>>(adj_row, n_edges);
    scan1_kernel<<<SCAN_NBLK, SCAN_T>>>();
    scan2_kernel<<<1, 64>>>();
    fill_kernel<<<edge16_blocks, TB>>>(adj_row, adj_col, adj_val, n_edges);

    // --- 2 full propagation layers in half ---
    spmm_half_kernel<<<row_blocks, TB>>>(embh, l1h);    // l1
    spmm_half_kernel<<<row_blocks, TB>>>(l1h,  l2h);    // l2

    // --- fused l3 + acc + dot at the sampled rows only ---
    final_kernel<<<pair_blocks, TB>>>(node_emb, user_ids, item_ids, out, n_pairs);
}